// round 4
// baseline (speedup 1.0000x reference)
#include <cuda_runtime.h>
#include <cstdint>

#define NN 50000
#define EE 800000

// ---------------- device scratch (static, allocation-free) ----------------
__device__ int   g_deg[NN];
__device__ int   g_off[NN + 1];
__device__ int   g_cur[NN];
__device__ int   g_csr[EE];
__device__ float g_s1[NN];
__device__ float g_s2[NN];
__device__ float g_avglog;
__device__ float g_UVX[NN * 192];   // cols 0-63: U, 64-127: V, 128-191: x@(Wx@lin)
__device__ float g_Agg[NN * 256];   // mean | min | max | std
__device__ float g_h0[NN * 64];     // layer-0 output (post relu)
__device__ float g_Wcat[2][64 * 192];
__device__ float g_Fcat[2][256 * 192];
__device__ float g_cb[2][64];

// ---------------- f32x2 helpers ----------------
__device__ __forceinline__ unsigned long long splat2(float x) {
    unsigned long long d;
    asm("mov.b64 %0, {%1, %1};" : "=l"(d) : "r"(__float_as_int(x)));
    return d;
}
__device__ __forceinline__ unsigned long long ffma2(unsigned long long a,
                                                    unsigned long long b,
                                                    unsigned long long c) {
    unsigned long long d;
    asm("fma.rn.f32x2 %0, %1, %2, %3;" : "=l"(d) : "l"(a), "l"(b), "l"(c));
    return d;
}
__device__ __forceinline__ float lohalf(unsigned long long u) {
    return __int_as_float((int)(unsigned)(u & 0xffffffffULL));
}
__device__ __forceinline__ float hihalf(unsigned long long u) {
    return __int_as_float((int)(unsigned)(u >> 32));
}

// ---------------- setup kernels ----------------
__global__ void k_zero() {
    int i = blockIdx.x * blockDim.x + threadIdx.x;
    if (i < NN) g_deg[i] = 0;
}

// edge_index is int32 (JAX x64 disabled downcasts jnp.int64 -> int32)
__global__ void k_deg(const int* __restrict__ ei) {
    int e = blockIdx.x * blockDim.x + threadIdx.x;
    if (e < EE) {
        unsigned d = (unsigned)ei[EE + e];
        if (d < NN) atomicAdd(&g_deg[d], 1);
    }
}

// single-block scan: offsets, cursor, avg_log, s1/s2
__global__ void k_scan() {
    __shared__ int    ssum[1024];
    __shared__ double sls[1024];
    __shared__ float  savg;
    int t = threadIdx.x;
    const int CH = (NN + 1023) / 1024;   // 49
    int base = t * CH;
    int sum = 0;
    double ls = 0.0;
    for (int i = 0; i < CH; i++) {
        int idx = base + i;
        if (idx < NN) {
            int d = g_deg[idx];
            sum += d;
            ls += (double)logf((float)d + 1.0f);
        }
    }
    ssum[t] = sum;
    sls[t] = ls;
    __syncthreads();
    // inclusive Hillis-Steele scan of ssum
    for (int off = 1; off < 1024; off <<= 1) {
        int v = (t >= off) ? ssum[t - off] : 0;
        __syncthreads();
        if (t >= off) ssum[t] += v;
        __syncthreads();
    }
    int excl = ssum[t] - sum;
    // reduce log-sum
    for (int off = 512; off > 0; off >>= 1) {
        if (t < off) sls[t] += sls[t + off];
        __syncthreads();
    }
    if (t == 0) {
        savg = (float)(sls[0] / (double)NN);
        g_avglog = savg;
        g_off[NN] = ssum[1023];
    }
    __syncthreads();
    float avg = savg;
    int run = excl;
    for (int i = 0; i < CH; i++) {
        int idx = base + i;
        if (idx < NN) {
            int d = g_deg[idx];
            g_off[idx] = run;
            g_cur[idx] = run;
            run += d;
            int dc = (d > 0) ? d : 1;
            float logd = logf((float)dc + 1.0f);
            g_s1[idx] = logd / avg;
            g_s2[idx] = avg / logd;
        }
    }
}

__global__ void k_fill(const int* __restrict__ ei) {
    int e = blockIdx.x * blockDim.x + threadIdx.x;
    if (e < EE) {
        unsigned d = (unsigned)ei[EE + e];
        unsigned s = (unsigned)ei[e];
        if (d < NN && s < NN) {
            int p = atomicAdd(&g_cur[d], 1);
            g_csr[p] = (int)s;
        }
    }
}

// fold weights: Wcat = [Wtop | Wbot | Wx@lin], Fcat = [W1@lin | W2@lin | W3@lin], cb
__global__ void k_fold(const float* __restrict__ preW, const float* __restrict__ postW,
                       const float* __restrict__ postb, const float* __restrict__ linW,
                       const float* __restrict__ linb, int layer) {
    int idx = blockIdx.x * blockDim.x + threadIdx.x;
    if (idx < 320 * 192) {
        int r = idx / 192, c = idx % 192;
        if (r < 64) {
            float v;
            if (c < 64) {
                v = preW[r * 64 + c];
            } else if (c < 128) {
                v = preW[(64 + r) * 64 + (c - 64)];
            } else {
                int f = c - 128;
                float s = 0.f;
                #pragma unroll 8
                for (int j = 0; j < 64; j++) s = fmaf(postW[r * 64 + j], linW[j * 64 + f], s);
                v = s;
            }
            g_Wcat[layer][r * 192 + c] = v;
        } else {
            int k = r - 64;        // 0..255
            int p = c / 64;        // which scale group
            int f = c % 64;
            int srow = 64 + p * 256 + k;
            float s = 0.f;
            #pragma unroll 8
            for (int j = 0; j < 64; j++) s = fmaf(postW[srow * 64 + j], linW[j * 64 + f], s);
            g_Fcat[layer][k * 192 + c] = s;
        }
    } else if (idx < 320 * 192 + 64) {
        int f = idx - 320 * 192;
        float s = 0.f;
        #pragma unroll 8
        for (int j = 0; j < 64; j++) s = fmaf(postb[j], linW[j * 64 + f], s);
        g_cb[layer][f] = s + linb[f];
    }
}

// ---------------- aggregation: one warp per node, CSR, no atomics ----------------
__global__ void __launch_bounds__(256) k_agg(const float* __restrict__ preb) {
    int w = (blockIdx.x * blockDim.x + threadIdx.x) >> 5;
    int l = threadIdx.x & 31;
    if (w >= NN) return;
    int o0 = g_off[w], o1 = g_off[w + 1];
    int dg = o1 - o0;
    const float* uvx = g_UVX;
    float c0 = uvx[w * 192 + l]      + preb[l];
    float c1 = uvx[w * 192 + 32 + l] + preb[32 + l];
    float s0 = 0.f, q0 = 0.f, s1 = 0.f, q1 = 0.f;
    float inf = __int_as_float(0x7f800000);
    float mn0 = inf, mn1 = inf, mx0 = -inf, mx1 = -inf;
    #pragma unroll 4
    for (int e = o0; e < o1; e++) {
        int j = g_csr[e];
        const float* vp = uvx + j * 192 + 64;
        float t0 = c0 + vp[l];
        float t1 = c1 + vp[32 + l];
        s0 += t0; q0 = fmaf(t0, t0, q0); mn0 = fminf(mn0, t0); mx0 = fmaxf(mx0, t0);
        s1 += t1; q1 = fmaf(t1, t1, q1); mn1 = fminf(mn1, t1); mx1 = fmaxf(mx1, t1);
    }
    float inv = 1.0f / (float)((dg > 0) ? dg : 1);
    float m0 = s0 * inv, m1 = s1 * inv;
    float v0 = q0 * inv - m0 * m0;
    float v1 = q1 * inv - m1 * m1;
    float sd0 = sqrtf(fmaxf(v0, 0.f) + 1e-5f);
    float sd1 = sqrtf(fmaxf(v1, 0.f) + 1e-5f);
    if (dg == 0) { mn0 = mn1 = mx0 = mx1 = 0.f; }
    float* arow = g_Agg + w * 256;
    arow[l]        = m0;  arow[32 + l]  = m1;
    arow[64 + l]   = mn0; arow[96 + l]  = mn1;
    arow[128 + l]  = mx0; arow[160 + l] = mx1;
    arow[192 + l]  = sd0; arow[224 + l] = sd1;
}

// ---------------- GEMM: C[M,192] = A[M,K] @ B[K,192], f32x2 accumulation ----------
// Tile: 128 rows x 192 cols, 256 threads, thread = 16 rows (8 row-pairs) x 6 cols.
// FUSE=true: K=256, A=g_Agg, B=g_Fcat[layer], epilogue combines s1/s2 + xf + cb (+relu)
// FUSE=false: K=64, B=g_Wcat[layer], writes g_UVX.
template <int K, bool FUSE>
__global__ void __launch_bounds__(256) k_gemm(const float* __restrict__ Aext, int useAext,
                                              int layer, float* __restrict__ Oext,
                                              int useOext, int relu) {
    constexpr int KC = 32;
    constexpr int TM = 128;
    __shared__ __align__(16) float As[KC][TM];
    __shared__ __align__(16) float Bs[KC][192];

    const float* A = FUSE ? g_Agg : (useAext ? Aext : g_h0);
    const float* B = FUSE ? g_Fcat[layer] : g_Wcat[layer];

    int tid = threadIdx.x;
    int tx = tid & 31;
    int ty = tid >> 5;
    int row0 = blockIdx.x * TM;
    int rbase = ty * 16;
    int f0 = tx * 2;

    unsigned long long acc[8][6];
    #pragma unroll
    for (int i = 0; i < 8; i++)
        #pragma unroll
        for (int j = 0; j < 6; j++) acc[i][j] = 0ULL;

    int lrow = tid >> 1;
    int lk = (tid & 1) << 4;

    #pragma unroll 1
    for (int k0 = 0; k0 < K; k0 += KC) {
        // stage A (transposed): 128 rows x 32 k
        float4 va[4];
        int arow = row0 + lrow;
        if (arow < NN) {
            const float4* ap = (const float4*)(A + arow * K + k0 + lk);
            va[0] = ap[0]; va[1] = ap[1]; va[2] = ap[2]; va[3] = ap[3];
        } else {
            float4 z = make_float4(0.f, 0.f, 0.f, 0.f);
            va[0] = z; va[1] = z; va[2] = z; va[3] = z;
        }
        #pragma unroll
        for (int i = 0; i < 4; i++) {
            As[lk + 4 * i + 0][lrow] = va[i].x;
            As[lk + 4 * i + 1][lrow] = va[i].y;
            As[lk + 4 * i + 2][lrow] = va[i].z;
            As[lk + 4 * i + 3][lrow] = va[i].w;
        }
        // stage B: 32 x 192
        {
            const float4* bg = (const float4*)(B + k0 * 192);
            float4* bs = (float4*)&Bs[0][0];
            #pragma unroll
            for (int i = 0; i < 6; i++) bs[tid + 256 * i] = bg[tid + 256 * i];
        }
        __syncthreads();
        #pragma unroll 8
        for (int k = 0; k < KC; k++) {
            unsigned long long a[8];
            #pragma unroll
            for (int rp = 0; rp < 8; rp++)
                a[rp] = *(const unsigned long long*)&As[k][rbase + 2 * rp];
            #pragma unroll
            for (int cg = 0; cg < 6; cg++) {
                int col = (cg >> 1) * 64 + f0 + (cg & 1);
                unsigned long long b2 = splat2(Bs[k][col]);
                #pragma unroll
                for (int rp = 0; rp < 8; rp++)
                    acc[rp][cg] = ffma2(a[rp], b2, acc[rp][cg]);
            }
        }
        __syncthreads();
    }

    if (!FUSE) {
        #pragma unroll
        for (int rp = 0; rp < 8; rp++) {
            int r = row0 + rbase + 2 * rp;
            if (r < NN) {
                #pragma unroll
                for (int g = 0; g < 3; g++) {
                    float2 v = make_float2(lohalf(acc[rp][2 * g]), lohalf(acc[rp][2 * g + 1]));
                    *(float2*)&g_UVX[r * 192 + g * 64 + f0] = v;
                }
            }
            if (r + 1 < NN) {
                #pragma unroll
                for (int g = 0; g < 3; g++) {
                    float2 v = make_float2(hihalf(acc[rp][2 * g]), hihalf(acc[rp][2 * g + 1]));
                    *(float2*)&g_UVX[(r + 1) * 192 + g * 64 + f0] = v;
                }
            }
        }
    } else {
        float* O = useOext ? Oext : g_h0;
        #pragma unroll
        for (int rp = 0; rp < 8; rp++) {
            #pragma unroll
            for (int h = 0; h < 2; h++) {
                int r = row0 + rbase + 2 * rp + h;
                if (r < NN) {
                    float a1 = g_s1[r], a2 = g_s2[r];
                    #pragma unroll
                    for (int c = 0; c < 2; c++) {
                        float z1 = h ? hihalf(acc[rp][c])     : lohalf(acc[rp][c]);
                        float z2 = h ? hihalf(acc[rp][2 + c]) : lohalf(acc[rp][2 + c]);
                        float z3 = h ? hihalf(acc[rp][4 + c]) : lohalf(acc[rp][4 + c]);
                        float v = z1 + a1 * z2 + a2 * z3
                                  + g_UVX[r * 192 + 128 + f0 + c] + g_cb[layer][f0 + c];
                        if (relu) v = fmaxf(v, 0.f);
                        O[r * 64 + f0 + c] = v;
                    }
                }
            }
        }
    }
}

// ---------------- launch ----------------
extern "C" void kernel_launch(void* const* d_in, const int* in_sizes, int n_in,
                              void* d_out, int out_size) {
    const float* x      = (const float*)d_in[0];
    const int*   ei     = (const int*)d_in[1];   // int32 edge_index [2, E]
    const float* preW0  = (const float*)d_in[2];
    const float* preb0  = (const float*)d_in[3];
    const float* postW0 = (const float*)d_in[4];
    const float* postb0 = (const float*)d_in[5];
    const float* linW0  = (const float*)d_in[6];
    const float* linb0  = (const float*)d_in[7];
    const float* preW1  = (const float*)d_in[8];
    const float* preb1  = (const float*)d_in[9];
    const float* postW1 = (const float*)d_in[10];
    const float* postb1 = (const float*)d_in[11];
    const float* linW1  = (const float*)d_in[12];
    const float* linb1  = (const float*)d_in[13];
    float* out = (float*)d_out;

    // CSR build + scalars
    k_zero<<<(NN + 255) / 256, 256>>>();
    k_deg<<<(EE + 255) / 256, 256>>>(ei);
    k_scan<<<1, 1024>>>();
    k_fill<<<(EE + 255) / 256, 256>>>(ei);

    // weight folding
    int foldT = 320 * 192 + 64;
    k_fold<<<(foldT + 255) / 256, 256>>>(preW0, postW0, postb0, linW0, linb0, 0);
    k_fold<<<(foldT + 255) / 256, 256>>>(preW1, postW1, postb1, linW1, linb1, 1);

    int gGrid = (NN + 127) / 128;
    int aGrid = (NN * 32 + 255) / 256;

    // layer 0
    k_gemm<64, false><<<gGrid, 256>>>(x, 1, 0, nullptr, 0, 0);
    k_agg<<<aGrid, 256>>>(preb0);
    k_gemm<256, true><<<gGrid, 256>>>(nullptr, 0, 0, nullptr, 0, 1);   // -> g_h0, relu

    // layer 1
    k_gemm<64, false><<<gGrid, 256>>>(nullptr, 0, 1, nullptr, 0, 0);   // A = g_h0
    k_agg<<<aGrid, 256>>>(preb1);
    k_gemm<256, true><<<gGrid, 256>>>(nullptr, 0, 1, out, 1, 0);       // -> d_out
}